// round 16
// baseline (speedup 1.0000x reference)
#include <cuda_runtime.h>

// Problem shapes (fixed)
#define BB 32
#define NN 4096
#define DD 8
#define NEE 2048
#define DEE 4
#define NSPLIT 8

// Device scratch (static globals; no allocation). Zero-initialized at module
// load; every kernel_launch call leaves masks zeroed again (k_combine tail),
// so the sequence is deterministic call-to-call.
__device__ unsigned g_mask_int[NN];
__device__ unsigned g_mask_ext[NEE];
__device__ long long g_list[BB][6784];   // premultiplied byte offsets rel. W_int
__device__ int g_cnt[BB];                // padded combined length (multiple of 16)
__device__ float g_part[NSPLIT][BB][NN]; // split-K partial sums
__device__ float g_zero[NN];             // stays all-zero; pad rows point here

// ---------------------------------------------------------------------------
// Kernel 1 (fused spike + mask): thread per (b,n).
// ---------------------------------------------------------------------------
__global__ void k_spikemask(const float* __restrict__ V, const float* __restrict__ a,
                            const float* __restrict__ Xd, const float* __restrict__ Xext,
                            const float* __restrict__ dmap_int,
                            const float* __restrict__ dmap_ext,
                            float* __restrict__ out) {
    int idx = blockIdx.x * blockDim.x + threadIdx.x;   // 0 .. B*N-1
    int b = idx >> 12;                                 // idx / NN
    int n = idx & (NN - 1);

    float v  = V[idx];
    float aa = a[idx];
    float th = __fadd_rn(1.0f, __fmul_rn(1.8f, aa));
    float x  = (__fadd_rn(v, -th) >= 0.0f) ? 1.0f : 0.0f;
    out[idx] = x;                                       // row 0: X
    out[2 * BB * NN + idx] = 0.98f * aa + x;            // row 2: a_new

    // internal source (b, n)
    {
        int del = 0;
#pragma unroll
        for (int d = 0; d < DD; d++)
            if (dmap_int[d * NN + n] > 0.5f) del = d;
        float xs = (del == 0) ? x : Xd[(size_t)(del - 1) * BB * NN + idx];
        if (xs > 0.5f) atomicOr(&g_mask_int[n], 1u << b);
    }
    // external source (b, n) for n < NE
    if (n < NEE) {
        int del = 0;
#pragma unroll
        for (int d = 0; d < DEE; d++)
            if (dmap_ext[d * NEE + n] > 0.5f) del = d;
        float xs = Xext[(size_t)del * BB * NEE + b * NEE + n];
        if (xs > 0.5f) atomicOr(&g_mask_ext[n], 1u << b);
    }
}

// ---------------------------------------------------------------------------
// Kernel 2: compaction into ONE combined offset list per batch.
// Entries are 64-bit byte offsets relative to W_int:
//   internal i -> i*N*4 ; external j -> (W_ext - W_int) + j*N*4 ;
//   padding    -> (g_zero - W_int)  (loads read zeros; no predicates needed).
// Padded to a multiple of 16.
// ---------------------------------------------------------------------------
__global__ void __launch_bounds__(256) k_compact(const float* __restrict__ W_int,
                                                 const float* __restrict__ W_ext) {
    int b = blockIdx.x;            // 0..31
    int tid = threadIdx.x;
    int w = tid >> 5, lane = tid & 31;
    unsigned lt = (lane == 0) ? 0u : (0xffffffffu >> (32 - lane));

    const long long ext_base = (long long)((const char*)W_ext - (const char*)W_int);
    const long long zero_off = (long long)((const char*)g_zero - (const char*)W_int);

    __shared__ int wcnt[8], wbase[8], s_total, s_base_ext;

    // ---- internal ----
    {
        int cnt = 0;
#pragma unroll
        for (int r = 0; r < 16; r++) {
            int i = (w * 16 + r) * 32 + lane;
            bool act = (g_mask_int[i] >> b) & 1u;
            cnt += __popc(__ballot_sync(0xffffffffu, act));
        }
        if (lane == 0) wcnt[w] = cnt;
        __syncthreads();
        if (tid == 0) {
            int s = 0;
#pragma unroll
            for (int j = 0; j < 8; j++) { wbase[j] = s; s += wcnt[j]; }
            s_total = s;
            s_base_ext = s;
        }
        __syncthreads();
        int base = wbase[w];
#pragma unroll
        for (int r = 0; r < 16; r++) {
            int i = (w * 16 + r) * 32 + lane;
            bool act = (g_mask_int[i] >> b) & 1u;
            unsigned bal = __ballot_sync(0xffffffffu, act);
            if (act) g_list[b][base + __popc(bal & lt)] = (long long)i * (NN * 4);
            base += __popc(bal);
        }
        __syncthreads();
    }

    // ---- external (appended) ----
    {
        int cnt = 0;
#pragma unroll
        for (int r = 0; r < 8; r++) {
            int i = (w * 8 + r) * 32 + lane;
            bool act = (g_mask_ext[i] >> b) & 1u;
            cnt += __popc(__ballot_sync(0xffffffffu, act));
        }
        if (lane == 0) wcnt[w] = cnt;
        __syncthreads();
        if (tid == 0) {
            int s = s_base_ext;
#pragma unroll
            for (int j = 0; j < 8; j++) { wbase[j] = s; s += wcnt[j]; }
            s_total = s;
        }
        __syncthreads();
        int base = wbase[w];
#pragma unroll
        for (int r = 0; r < 8; r++) {
            int i = (w * 8 + r) * 32 + lane;
            bool act = (g_mask_ext[i] >> b) & 1u;
            unsigned bal = __ballot_sync(0xffffffffu, act);
            if (act) g_list[b][base + __popc(bal & lt)] = ext_base + (long long)i * (NN * 4);
            base += __popc(bal);
        }
        __syncthreads();
        int t = s_total;
        int padded = (t + 15) & ~15;
        if (t + tid < padded) g_list[b][t + tid] = zero_off;
        if (tid == 0) g_cnt[b] = padded;
    }
}

// ---------------------------------------------------------------------------
// Kernel 3: split-K sparse row-gather, float4 per thread.
// grid (N/512, B, NSPLIT) = (8, 32, 8) = 2048 blocks (~55 warps/SM).
// Same 16-source window; each load is LDG.128 so the ~3-4 loads ptxas keeps
// in flight per thread carry 2x the bytes of the float2 version, and issue
// per delivered byte drops ~30%.
// ---------------------------------------------------------------------------
__global__ void k_gather(const float* __restrict__ W_int,
                         float* __restrict__ out) {
    const int b = blockIdx.y;
    const int s = blockIdx.z;
    const int nwin = g_cnt[b] >> 4;
    const long long* __restrict__ lst = g_list[b];

    const int n4 = (blockIdx.x * 128 + threadIdx.x) * 4;  // column quad
    const char* base = (const char*)W_int + (size_t)n4 * 4;

    float4 a0 = make_float4(0.f, 0.f, 0.f, 0.f);
    float4 a1 = make_float4(0.f, 0.f, 0.f, 0.f);
    float4 a2 = make_float4(0.f, 0.f, 0.f, 0.f);
    float4 a3 = make_float4(0.f, 0.f, 0.f, 0.f);

    for (int j = s; j < nwin; j += NSPLIT) {
        const int k = j * 16;
        long long o[16];
#pragma unroll
        for (int u = 0; u < 16; u++) o[u] = __ldg(lst + k + u);
        float4 w[16];
#pragma unroll
        for (int u = 0; u < 16; u++)
            w[u] = __ldg((const float4*)(base + o[u]));
#pragma unroll
        for (int u = 0; u < 16; u += 4) {
            a0.x += w[u].x;     a0.y += w[u].y;     a0.z += w[u].z;     a0.w += w[u].w;
            a1.x += w[u + 1].x; a1.y += w[u + 1].y; a1.z += w[u + 1].z; a1.w += w[u + 1].w;
            a2.x += w[u + 2].x; a2.y += w[u + 2].y; a2.z += w[u + 2].z; a2.w += w[u + 2].w;
            a3.x += w[u + 3].x; a3.y += w[u + 3].y; a3.z += w[u + 3].z; a3.w += w[u + 3].w;
        }
    }

    float4 r;
    r.x = (a0.x + a1.x) + (a2.x + a3.x);
    r.y = (a0.y + a1.y) + (a2.y + a3.y);
    r.z = (a0.z + a1.z) + (a2.z + a3.z);
    r.w = (a0.w + a1.w) + (a2.w + a3.w);
    *(float4*)(&g_part[s][b][n4]) = r;
}

// ---------------------------------------------------------------------------
// Kernel 4: combine partials + leak/reset -> V_new (row 1), fixed order.
// Scalar, one element per thread (max thread count = max MLP for this
// latency-bound kernel). Also re-zeroes the masks for the next call.
// ---------------------------------------------------------------------------
__global__ void k_combine(const float* __restrict__ V, float* __restrict__ out) {
    int idx = blockIdx.x * blockDim.x + threadIdx.x;   // 0 .. B*N-1
    int b = idx >> 12;
    int n = idx & (NN - 1);
    float x = out[idx];                                 // X (row 0)
    float acc = 0.95f * V[idx] * (1.0f - x);
    acc += g_part[0][b][n];
    acc += g_part[1][b][n];
    acc += g_part[2][b][n];
    acc += g_part[3][b][n];
    acc += g_part[4][b][n];
    acc += g_part[5][b][n];
    acc += g_part[6][b][n];
    acc += g_part[7][b][n];
    out[BB * NN + idx] = acc;                           // row 1: V_new

    if (idx < NN)  g_mask_int[idx] = 0u;
    if (idx < NEE) g_mask_ext[idx] = 0u;
}

// ---------------------------------------------------------------------------
extern "C" void kernel_launch(void* const* d_in, const int* in_sizes, int n_in,
                              void* d_out, int out_size) {
    const float* V        = (const float*)d_in[0];   // [B,N]
    const float* a        = (const float*)d_in[1];   // [B,N]
    const float* Xd       = (const float*)d_in[2];   // [D,B,N]
    const float* Xext     = (const float*)d_in[3];   // [DE,B,NE]
    const float* W_int    = (const float*)d_in[4];   // [N,N]
    const float* W_ext    = (const float*)d_in[5];   // [NE,N]
    const float* dmap_int = (const float*)d_in[6];   // [D,N]
    const float* dmap_ext = (const float*)d_in[7];   // [DE,NE]
    float* out = (float*)d_out;                      // [3,B,N]

    k_spikemask<<<(BB * NN) / 256, 256>>>(V, a, Xd, Xext, dmap_int, dmap_ext, out);
    k_compact<<<BB, 256>>>(W_int, W_ext);
    dim3 grid(NN / 512, BB, NSPLIT);
    k_gather<<<grid, 128>>>(W_int, out);
    k_combine<<<(BB * NN) / 256, 256>>>(V, out);
}

// round 17
// speedup vs baseline: 1.0494x; 1.0494x over previous
#include <cuda_runtime.h>

// Problem shapes (fixed)
#define BB 32
#define NN 4096
#define DD 8
#define NEE 2048
#define DEE 4
#define NSPLIT 8
#define MAXWIN 48   // max 16-source windows per split: 6144/16/8

// Device scratch (static globals; no allocation). Zero-initialized at module
// load; every kernel_launch call leaves masks zeroed again (k_combine tail),
// so the sequence is deterministic call-to-call.
__device__ unsigned g_mask_int[NN];
__device__ unsigned g_mask_ext[NEE];
__device__ long long g_list[BB][6784];   // premultiplied byte offsets rel. W_int
__device__ int g_cnt[BB];                // padded combined length (multiple of 16)
__device__ float g_part[NSPLIT][BB][NN]; // split-K partial sums
__device__ float g_zero[NN];             // stays all-zero; pad rows point here

// ---------------------------------------------------------------------------
// Kernel 1 (fused spike + mask): thread per (b,n).
// ---------------------------------------------------------------------------
__global__ void k_spikemask(const float* __restrict__ V, const float* __restrict__ a,
                            const float* __restrict__ Xd, const float* __restrict__ Xext,
                            const float* __restrict__ dmap_int,
                            const float* __restrict__ dmap_ext,
                            float* __restrict__ out) {
    int idx = blockIdx.x * blockDim.x + threadIdx.x;   // 0 .. B*N-1
    int b = idx >> 12;                                 // idx / NN
    int n = idx & (NN - 1);

    float v  = V[idx];
    float aa = a[idx];
    float th = __fadd_rn(1.0f, __fmul_rn(1.8f, aa));
    float x  = (__fadd_rn(v, -th) >= 0.0f) ? 1.0f : 0.0f;
    out[idx] = x;                                       // row 0: X
    out[2 * BB * NN + idx] = 0.98f * aa + x;            // row 2: a_new

    // internal source (b, n)
    {
        int del = 0;
#pragma unroll
        for (int d = 0; d < DD; d++)
            if (dmap_int[d * NN + n] > 0.5f) del = d;
        float xs = (del == 0) ? x : Xd[(size_t)(del - 1) * BB * NN + idx];
        if (xs > 0.5f) atomicOr(&g_mask_int[n], 1u << b);
    }
    // external source (b, n) for n < NE
    if (n < NEE) {
        int del = 0;
#pragma unroll
        for (int d = 0; d < DEE; d++)
            if (dmap_ext[d * NEE + n] > 0.5f) del = d;
        float xs = Xext[(size_t)del * BB * NEE + b * NEE + n];
        if (xs > 0.5f) atomicOr(&g_mask_ext[n], 1u << b);
    }
}

// ---------------------------------------------------------------------------
// Kernel 2: compaction into ONE combined offset list per batch.
// Entries are 64-bit byte offsets relative to W_int:
//   internal i -> i*N*4 ; external j -> (W_ext - W_int) + j*N*4 ;
//   padding    -> (g_zero - W_int)  (loads read zeros; no predicates needed).
// Padded to a multiple of 16.
// ---------------------------------------------------------------------------
__global__ void __launch_bounds__(256) k_compact(const float* __restrict__ W_int,
                                                 const float* __restrict__ W_ext) {
    int b = blockIdx.x;            // 0..31
    int tid = threadIdx.x;
    int w = tid >> 5, lane = tid & 31;
    unsigned lt = (lane == 0) ? 0u : (0xffffffffu >> (32 - lane));

    const long long ext_base = (long long)((const char*)W_ext - (const char*)W_int);
    const long long zero_off = (long long)((const char*)g_zero - (const char*)W_int);

    __shared__ int wcnt[8], wbase[8], s_total, s_base_ext;

    // ---- internal ----
    {
        int cnt = 0;
#pragma unroll
        for (int r = 0; r < 16; r++) {
            int i = (w * 16 + r) * 32 + lane;
            bool act = (g_mask_int[i] >> b) & 1u;
            cnt += __popc(__ballot_sync(0xffffffffu, act));
        }
        if (lane == 0) wcnt[w] = cnt;
        __syncthreads();
        if (tid == 0) {
            int s = 0;
#pragma unroll
            for (int j = 0; j < 8; j++) { wbase[j] = s; s += wcnt[j]; }
            s_total = s;
            s_base_ext = s;
        }
        __syncthreads();
        int base = wbase[w];
#pragma unroll
        for (int r = 0; r < 16; r++) {
            int i = (w * 16 + r) * 32 + lane;
            bool act = (g_mask_int[i] >> b) & 1u;
            unsigned bal = __ballot_sync(0xffffffffu, act);
            if (act) g_list[b][base + __popc(bal & lt)] = (long long)i * (NN * 4);
            base += __popc(bal);
        }
        __syncthreads();
    }

    // ---- external (appended) ----
    {
        int cnt = 0;
#pragma unroll
        for (int r = 0; r < 8; r++) {
            int i = (w * 8 + r) * 32 + lane;
            bool act = (g_mask_ext[i] >> b) & 1u;
            cnt += __popc(__ballot_sync(0xffffffffu, act));
        }
        if (lane == 0) wcnt[w] = cnt;
        __syncthreads();
        if (tid == 0) {
            int s = s_base_ext;
#pragma unroll
            for (int j = 0; j < 8; j++) { wbase[j] = s; s += wcnt[j]; }
            s_total = s;
        }
        __syncthreads();
        int base = wbase[w];
#pragma unroll
        for (int r = 0; r < 8; r++) {
            int i = (w * 8 + r) * 32 + lane;
            bool act = (g_mask_ext[i] >> b) & 1u;
            unsigned bal = __ballot_sync(0xffffffffu, act);
            if (act) g_list[b][base + __popc(bal & lt)] = ext_base + (long long)i * (NN * 4);
            base += __popc(bal);
        }
        __syncthreads();
        int t = s_total;
        int padded = (t + 15) & ~15;
        if (t + tid < padded) g_list[b][t + tid] = zero_off;
        if (tid == 0) g_cnt[b] = padded;
    }
}

// ---------------------------------------------------------------------------
// Kernel 3: split-K sparse row-gather, float2 per thread (R14 body) with the
// block's list slice staged in shared memory. grid (16, 32, 8), 128 threads.
// Prologue: <=1 LDG/thread stages this split's windows (typ. ~64 entries);
// the hot loop reads offsets via LDS broadcast, halving L1 wavefront use.
// ---------------------------------------------------------------------------
__global__ void k_gather(const float* __restrict__ W_int,
                         float* __restrict__ out) {
    __shared__ alignas(16) long long s_off[MAXWIN * 16];

    const int b = blockIdx.y;
    const int s = blockIdx.z;
    const int nwin = g_cnt[b] >> 4;
    const long long* __restrict__ lst = g_list[b];

    const int nloc = (nwin > s) ? ((nwin - s + NSPLIT - 1) / NSPLIT) : 0;
    for (int t = threadIdx.x; t < nloc * 16; t += 128) {
        int w = t >> 4;
        s_off[t] = lst[(s + w * NSPLIT) * 16 + (t & 15)];
    }
    __syncthreads();

    const int n2 = (blockIdx.x * 128 + threadIdx.x) * 2;  // column pair
    const char* base = (const char*)W_int + (size_t)n2 * 4;

    float ax0 = 0.f, ay0 = 0.f, ax1 = 0.f, ay1 = 0.f;
    float ax2 = 0.f, ay2 = 0.f, ax3 = 0.f, ay3 = 0.f;

    for (int wnd = 0; wnd < nloc; wnd++) {
        const long long* so = s_off + wnd * 16;
        long long o[16];
#pragma unroll
        for (int u = 0; u < 16; u++) o[u] = so[u];
        float2 w[16];
#pragma unroll
        for (int u = 0; u < 16; u++)
            w[u] = __ldg((const float2*)(base + o[u]));
#pragma unroll
        for (int u = 0; u < 16; u += 4) {
            ax0 += w[u].x;     ay0 += w[u].y;
            ax1 += w[u + 1].x; ay1 += w[u + 1].y;
            ax2 += w[u + 2].x; ay2 += w[u + 2].y;
            ax3 += w[u + 3].x; ay3 += w[u + 3].y;
        }
    }

    float2 r;
    r.x = (ax0 + ax1) + (ax2 + ax3);
    r.y = (ay0 + ay1) + (ay2 + ay3);
    *(float2*)(&g_part[s][b][n2]) = r;
}

// ---------------------------------------------------------------------------
// Kernel 4: combine partials + leak/reset -> V_new (row 1), fixed order.
// Scalar, one element per thread. Also re-zeroes the masks for the next call.
// ---------------------------------------------------------------------------
__global__ void k_combine(const float* __restrict__ V, float* __restrict__ out) {
    int idx = blockIdx.x * blockDim.x + threadIdx.x;   // 0 .. B*N-1
    int b = idx >> 12;
    int n = idx & (NN - 1);
    float x = out[idx];                                 // X (row 0)
    float acc = 0.95f * V[idx] * (1.0f - x);
    acc += g_part[0][b][n];
    acc += g_part[1][b][n];
    acc += g_part[2][b][n];
    acc += g_part[3][b][n];
    acc += g_part[4][b][n];
    acc += g_part[5][b][n];
    acc += g_part[6][b][n];
    acc += g_part[7][b][n];
    out[BB * NN + idx] = acc;                           // row 1: V_new

    if (idx < NN)  g_mask_int[idx] = 0u;
    if (idx < NEE) g_mask_ext[idx] = 0u;
}

// ---------------------------------------------------------------------------
extern "C" void kernel_launch(void* const* d_in, const int* in_sizes, int n_in,
                              void* d_out, int out_size) {
    const float* V        = (const float*)d_in[0];   // [B,N]
    const float* a        = (const float*)d_in[1];   // [B,N]
    const float* Xd       = (const float*)d_in[2];   // [D,B,N]
    const float* Xext     = (const float*)d_in[3];   // [DE,B,NE]
    const float* W_int    = (const float*)d_in[4];   // [N,N]
    const float* W_ext    = (const float*)d_in[5];   // [NE,N]
    const float* dmap_int = (const float*)d_in[6];   // [D,N]
    const float* dmap_ext = (const float*)d_in[7];   // [DE,NE]
    float* out = (float*)d_out;                      // [3,B,N]

    k_spikemask<<<(BB * NN) / 256, 256>>>(V, a, Xd, Xext, dmap_int, dmap_ext, out);
    k_compact<<<BB, 256>>>(W_int, W_ext);
    dim3 grid(NN / 256, BB, NSPLIT);
    k_gather<<<grid, 128>>>(W_int, out);
    k_combine<<<(BB * NN) / 256, 256>>>(V, out);
}